// round 10
// baseline (speedup 1.0000x reference)
#include <cuda_runtime.h>

// SyntheticTripletLoss closed form: per valid row only
//   pp=<p,p>, tt=<t,t>, pt=<p,t>
//   sim_pn = (pp - pt^2) / max(sqrt(pp - 2pt^2 + pt^2*tt), EPS)
//   loss   = max(MARGIN + sim_pn - pt, 0); mean over valid rows.
//
// R10: cycle-minimized single-wave kernel. Evidence says the chip runs these
// 12us kernels at idle DVFS clocks, so the kernel is CYCLE-bound: the
// single-address ticket atomic (2048 x 0.854cyc serialization), the 2-wave
// CTA structure, and the 2048-partial tail are the remaining fat. Fix: 592
// CTAs (one resident wave), grid-stride over valid rows, 592 tickets, 592
// partials.

#define MARGIN 0.5f
#define EPS_N 1e-12f

static constexpr int B = 32;
static constexpr int T = 512;
static constexpr int D = 512;
static constexpr int WARPS_PER_BLOCK = 8;
static constexpr int THREADS = WARPS_PER_BLOCK * 32;   // 256
static constexpr int NBLK = 592;                       // 4 CTAs/SM, one wave
static constexpr int TOTAL_WARPS = NBLK * WARPS_PER_BLOCK;  // 4736

__device__ float g_partials[NBLK];
__device__ unsigned int g_ticket;   // zero-init; last block resets each run

__global__ __launch_bounds__(THREADS)
void triplet_wave_kernel(const float* __restrict__ preds,
                         const float* __restrict__ targets,
                         const int* __restrict__ lengths,
                         float* __restrict__ out) {
    __shared__ int   s_pre[B + 1];           // exclusive prefix of lengths
    __shared__ float s_warp[WARPS_PER_BLOCK];
    __shared__ bool  s_is_last;

    const int warp = threadIdx.x >> 5;
    const int lane = threadIdx.x & 31;

    // Warp 0: inclusive shuffle-scan of lengths[0..31] -> prefix in smem.
    if (warp == 0) {
        int v = __ldg(&lengths[lane]);
        int s = v;
        #pragma unroll
        for (int off = 1; off < 32; off <<= 1) {
            int n = __shfl_up_sync(0xffffffffu, s, off);
            if (lane >= off) s += n;
        }
        s_pre[lane + 1] = s;
        if (lane == 0) s_pre[0] = 0;
    }
    __syncthreads();

    const int total = s_pre[B];              // number of valid rows
    const int gw    = blockIdx.x * WARPS_PER_BLOCK + warp;

    float acc = 0.0f;

    // Grid-stride over valid-row indices; <=4 iterations worst case.
    for (int vid = gw; vid < total; vid += TOTAL_WARPS) {
        // binary search: largest b with s_pre[b] <= vid
        int lo = 0, hi = B;
        #pragma unroll
        for (int i = 0; i < 5; i++) {        // log2(32)
            int mid = (lo + hi) >> 1;
            if (s_pre[mid] <= vid) lo = mid; else hi = mid;
        }
        const int row = lo * T + (vid - s_pre[lo]);

        const float4* __restrict__ p4 =
            reinterpret_cast<const float4*>(preds + (size_t)row * D);
        const float4* __restrict__ t4 =
            reinterpret_cast<const float4*>(targets + (size_t)row * D);

        float4 a0 = __ldg(p4 + lane);
        float4 a1 = __ldg(p4 + lane + 32);
        float4 a2 = __ldg(p4 + lane + 64);
        float4 a3 = __ldg(p4 + lane + 96);
        float4 c0 = __ldg(t4 + lane);
        float4 c1 = __ldg(t4 + lane + 32);
        float4 c2 = __ldg(t4 + lane + 64);
        float4 c3 = __ldg(t4 + lane + 96);

        float pp = 0.f, tt = 0.f, pt = 0.f;
        #define ACC(a, c)                                                        \
            pp = fmaf(a.x, a.x, fmaf(a.y, a.y, fmaf(a.z, a.z, fmaf(a.w, a.w, pp)))); \
            tt = fmaf(c.x, c.x, fmaf(c.y, c.y, fmaf(c.z, c.z, fmaf(c.w, c.w, tt)))); \
            pt = fmaf(a.x, c.x, fmaf(a.y, c.y, fmaf(a.z, c.z, fmaf(a.w, c.w, pt))));
        ACC(a0, c0) ACC(a1, c1) ACC(a2, c2) ACC(a3, c3)
        #undef ACC

        #pragma unroll
        for (int off = 16; off; off >>= 1) {
            pp += __shfl_xor_sync(0xffffffffu, pp, off);
            tt += __shfl_xor_sync(0xffffffffu, tt, off);
            pt += __shfl_xor_sync(0xffffffffu, pt, off);
        }

        float pt2  = pt * pt;
        float n2   = fmaxf(pp - 2.0f * pt2 + pt2 * tt, 0.0f);
        float norm = fmaxf(sqrtf(n2), EPS_N);
        acc += fmaxf(MARGIN + (pp - pt2) / norm - pt, 0.0f);
    }

    // ---- block partial (fixed slot: deterministic) + acq_rel ticket ----
    if (lane == 0) s_warp[warp] = acc;
    __syncthreads();

    if (threadIdx.x == 0) {
        float sum = 0.f;
        #pragma unroll
        for (int i = 0; i < WARPS_PER_BLOCK; i++) sum += s_warp[i];
        g_partials[blockIdx.x] = sum;
        unsigned int old;
        asm volatile("atom.acq_rel.gpu.global.add.u32 %0, [%1], 1;"
                     : "=r"(old) : "l"(&g_ticket) : "memory");
        s_is_last = (old == (unsigned int)(NBLK - 1));
    }
    __syncthreads();
    if (!s_is_last) return;

    // ---- last block: reduce 592 partials (L2-resident), fixed order ----
    __shared__ float s_red[THREADS];
    float sum = 0.f;
    for (int i = threadIdx.x; i < NBLK; i += THREADS)
        sum += __ldcg(&g_partials[i]);
    s_red[threadIdx.x] = sum;
    __syncthreads();
    #pragma unroll
    for (int off = THREADS / 2; off; off >>= 1) {
        if (threadIdx.x < off) s_red[threadIdx.x] += s_red[threadIdx.x + off];
        __syncthreads();
    }
    if (threadIdx.x == 0) {
        out[0] = s_red[0] / (float)total;
        g_ticket = 0;   // reset for next graph replay
    }
}

extern "C" void kernel_launch(void* const* d_in, const int* in_sizes, int n_in,
                              void* d_out, int out_size) {
    const float* preds   = (const float*)d_in[0];
    const float* targets = (const float*)d_in[1];
    const int*   lengths = (const int*)d_in[2];
    float* out = (float*)d_out;

    triplet_wave_kernel<<<NBLK, THREADS>>>(preds, targets, lengths, out);
}

// round 11
// speedup vs baseline: 1.0029x; 1.0029x over previous
#include <cuda_runtime.h>
#include <cstdint>

// SyntheticTripletLoss closed form: per valid row only
//   pp=<p,p>, tt=<t,t>, pt=<p,t>
//   sim_pn = (pp - pt^2) / max(sqrt(pp - 2pt^2 + pt^2*tt), EPS)
//   loss   = max(MARGIN + sim_pn - pt, 0); mean over valid rows.
//
// R11: all-256-bit streaming. Model: the 2.5 TB/s wall == (per-SM ~64
// outstanding LDG entries x 128B) / ~530ns DRAM latency. If the cap counts
// ENTRIES, 256-bit LDGs (v8.b32) double bytes-in-flight -> ~2x BW. Both
// tensors via ld.global.nc.L2::evict_last.v8.b32; balanced valid-row
// mapping (R9) otherwise unchanged.

#define MARGIN 0.5f
#define EPS_N 1e-12f

static constexpr int B = 32;
static constexpr int T = 512;
static constexpr int D = 512;
static constexpr int WARPS_PER_BLOCK = 8;
static constexpr int THREADS = WARPS_PER_BLOCK * 32;    // 256
static constexpr int ROWS = B * T;                      // 16384
static constexpr int NBLOCKS = ROWS / WARPS_PER_BLOCK;  // 2048 (worst case)

__device__ float g_partials[NBLOCKS];
__device__ unsigned int g_ticket;   // zero-init; last block resets each run

// 256-bit non-coherent global load (evict_last: required modifier pairing,
// and keeps inputs L2-warm across graph replays if the policy sticks).
__device__ __forceinline__ void ldg256(const float* p, float* v) {
    uint32_t r0, r1, r2, r3, r4, r5, r6, r7;
    asm volatile(
        "ld.global.nc.L2::evict_last.v8.b32 {%0,%1,%2,%3,%4,%5,%6,%7}, [%8];"
        : "=r"(r0), "=r"(r1), "=r"(r2), "=r"(r3),
          "=r"(r4), "=r"(r5), "=r"(r6), "=r"(r7)
        : "l"(p));
    v[0] = __uint_as_float(r0); v[1] = __uint_as_float(r1);
    v[2] = __uint_as_float(r2); v[3] = __uint_as_float(r3);
    v[4] = __uint_as_float(r4); v[5] = __uint_as_float(r5);
    v[6] = __uint_as_float(r6); v[7] = __uint_as_float(r7);
}

__global__ __launch_bounds__(THREADS)
void triplet_v8_kernel(const float* __restrict__ preds,
                       const float* __restrict__ targets,
                       const int* __restrict__ lengths,
                       float* __restrict__ out) {
    __shared__ int   s_pre[B + 1];            // exclusive prefix of lengths
    __shared__ float s_warp[WARPS_PER_BLOCK];
    __shared__ bool  s_is_last;

    const int warp = threadIdx.x >> 5;
    const int lane = threadIdx.x & 31;

    // Warp 0: inclusive shuffle-scan of lengths[0..31] -> prefix in smem.
    if (warp == 0) {
        int v = __ldg(&lengths[lane]);
        int s = v;
        #pragma unroll
        for (int off = 1; off < 32; off <<= 1) {
            int n = __shfl_up_sync(0xffffffffu, s, off);
            if (lane >= off) s += n;
        }
        s_pre[lane + 1] = s;
        if (lane == 0) s_pre[0] = 0;
    }
    __syncthreads();

    const int total = s_pre[B];       // number of valid rows
    const int vid   = blockIdx.x * WARPS_PER_BLOCK + warp;

    float loss = 0.0f;

    if (vid < total) {
        // binary search: largest b with s_pre[b] <= vid
        int lo = 0, hi = B;
        #pragma unroll
        for (int i = 0; i < 5; i++) {
            int mid = (lo + hi) >> 1;
            if (s_pre[mid] <= vid) lo = mid; else hi = mid;
        }
        const int row = lo * T + (vid - s_pre[lo]);

        const float* __restrict__ pr = preds   + (size_t)row * D;
        const float* __restrict__ tr = targets + (size_t)row * D;

        // 512 floats / 32 lanes = 16 floats = 2 x v8 per tensor per lane.
        // 4 LDG entries per thread, 256B/warp-entry: front-batch all 4.
        float a[16], c[16];
        ldg256(pr + lane * 8, a);
        ldg256(pr + 256 + lane * 8, a + 8);
        ldg256(tr + lane * 8, c);
        ldg256(tr + 256 + lane * 8, c + 8);

        float pp = 0.f, tt = 0.f, pt = 0.f;
        #pragma unroll
        for (int i = 0; i < 16; i++) {
            pp = fmaf(a[i], a[i], pp);
            tt = fmaf(c[i], c[i], tt);
            pt = fmaf(a[i], c[i], pt);
        }

        #pragma unroll
        for (int off = 16; off; off >>= 1) {
            pp += __shfl_xor_sync(0xffffffffu, pp, off);
            tt += __shfl_xor_sync(0xffffffffu, tt, off);
            pt += __shfl_xor_sync(0xffffffffu, pt, off);
        }

        float pt2  = pt * pt;
        float n2   = fmaxf(pp - 2.0f * pt2 + pt2 * tt, 0.0f);
        float norm = fmaxf(sqrtf(n2), EPS_N);
        loss = fmaxf(MARGIN + (pp - pt2) / norm - pt, 0.0f);
    }

    // ---- block partial (fixed slot: deterministic) + acq_rel ticket ----
    if (lane == 0) s_warp[warp] = loss;
    __syncthreads();

    if (threadIdx.x == 0) {
        float sum = 0.f;
        #pragma unroll
        for (int i = 0; i < WARPS_PER_BLOCK; i++) sum += s_warp[i];
        g_partials[blockIdx.x] = sum;
        unsigned int old;
        asm volatile("atom.acq_rel.gpu.global.add.u32 %0, [%1], 1;"
                     : "=r"(old) : "l"(&g_ticket) : "memory");
        s_is_last = (old == (unsigned int)(NBLOCKS - 1));
    }
    __syncthreads();
    if (!s_is_last) return;

    // ---- last block: reduce 2048 partials (L2-resident), fixed order ----
    __shared__ float s_red[THREADS];
    float sum = 0.f;
    #pragma unroll
    for (int k = 0; k < NBLOCKS / THREADS; k++)
        sum += __ldcg(&g_partials[threadIdx.x + k * THREADS]);
    s_red[threadIdx.x] = sum;
    __syncthreads();
    #pragma unroll
    for (int off = THREADS / 2; off; off >>= 1) {
        if (threadIdx.x < off) s_red[threadIdx.x] += s_red[threadIdx.x + off];
        __syncthreads();
    }
    if (threadIdx.x == 0) {
        out[0] = s_red[0] / (float)total;
        g_ticket = 0;   // reset for next graph replay
    }
}

extern "C" void kernel_launch(void* const* d_in, const int* in_sizes, int n_in,
                              void* d_out, int out_size) {
    const float* preds   = (const float*)d_in[0];
    const float* targets = (const float*)d_in[1];
    const int*   lengths = (const int*)d_in[2];
    float* out = (float*)d_out;

    triplet_v8_kernel<<<NBLOCKS, THREADS>>>(preds, targets, lengths, out);
}

// round 12
// speedup vs baseline: 1.0238x; 1.0208x over previous
#include <cuda_runtime.h>

// SyntheticTripletLoss closed form: per valid row only
//   pp=<p,p>, tt=<t,t>, pt=<p,t>
//   sim_pn = (pp - pt^2) / max(sqrt(pp - 2pt^2 + pt^2*tt), EPS)
//   loss   = max(MARGIN + sim_pn - pt, 0); mean over valid rows.
//
// R12: cycle-floor kernel. Conclusion from R2-R11: streaming is pinned at the
// clock-invariant LTS cap (~6300 B/cyc) at NAT-idle clocks; bytes (33.6MB of
// valid rows) are irreducible. Only remaining fat is sync overhead:
// 512-thread blocks halve the block count -> 1024 ticket atomics and a
// 1024-partial tail (vs 2048), same streaming body as the best kernel (R8).

#define MARGIN 0.5f
#define EPS_N 1e-12f

static constexpr int B = 32;
static constexpr int T = 512;
static constexpr int D = 512;
static constexpr int WARPS_PER_BLOCK = 16;
static constexpr int THREADS = WARPS_PER_BLOCK * 32;    // 512
static constexpr int ROWS = B * T;                      // 16384
static constexpr int NBLOCKS = ROWS / WARPS_PER_BLOCK;  // 1024

__device__ float g_partials[NBLOCKS];
__device__ unsigned int g_ticket;   // zero-init; last block resets each run

__global__ __launch_bounds__(THREADS)
void triplet_floor_kernel(const float* __restrict__ preds,
                          const float* __restrict__ targets,
                          const int* __restrict__ lengths,
                          float* __restrict__ out) {
    const int warp = threadIdx.x >> 5;
    const int lane = threadIdx.x & 31;
    const int row  = blockIdx.x * WARPS_PER_BLOCK + warp;
    const int b    = row >> 9;        // row / T
    const int t    = row & (T - 1);   // row % T

    float loss = 0.0f;

    if (t < __ldg(&lengths[b])) {
        const float4* __restrict__ p4 =
            reinterpret_cast<const float4*>(preds + (size_t)row * D);
        const float4* __restrict__ t4 =
            reinterpret_cast<const float4*>(targets + (size_t)row * D);

        // 512 floats / 32 lanes = 4 float4 per lane per tensor; front-batch
        // all 8 loads for MLP.
        float4 a0 = __ldg(p4 + lane);
        float4 a1 = __ldg(p4 + lane + 32);
        float4 a2 = __ldg(p4 + lane + 64);
        float4 a3 = __ldg(p4 + lane + 96);
        float4 c0 = __ldg(t4 + lane);
        float4 c1 = __ldg(t4 + lane + 32);
        float4 c2 = __ldg(t4 + lane + 64);
        float4 c3 = __ldg(t4 + lane + 96);

        float pp = 0.f, tt = 0.f, pt = 0.f;
        #define ACC(a, c)                                                        \
            pp = fmaf(a.x, a.x, fmaf(a.y, a.y, fmaf(a.z, a.z, fmaf(a.w, a.w, pp)))); \
            tt = fmaf(c.x, c.x, fmaf(c.y, c.y, fmaf(c.z, c.z, fmaf(c.w, c.w, tt)))); \
            pt = fmaf(a.x, c.x, fmaf(a.y, c.y, fmaf(a.z, c.z, fmaf(a.w, c.w, pt))));
        ACC(a0, c0) ACC(a1, c1) ACC(a2, c2) ACC(a3, c3)
        #undef ACC

        #pragma unroll
        for (int off = 16; off; off >>= 1) {
            pp += __shfl_xor_sync(0xffffffffu, pp, off);
            tt += __shfl_xor_sync(0xffffffffu, tt, off);
            pt += __shfl_xor_sync(0xffffffffu, pt, off);
        }

        float pt2  = pt * pt;
        float n2   = fmaxf(pp - 2.0f * pt2 + pt2 * tt, 0.0f);
        float norm = fmaxf(sqrtf(n2), EPS_N);
        loss = fmaxf(MARGIN + (pp - pt2) / norm - pt, 0.0f);
    }

    // ---- block partial (fixed slot: deterministic) + acq_rel ticket ----
    __shared__ float s_warp[WARPS_PER_BLOCK];
    __shared__ bool  s_is_last;
    if (lane == 0) s_warp[warp] = loss;
    __syncthreads();

    if (threadIdx.x == 0) {
        float sum = 0.f;
        #pragma unroll
        for (int i = 0; i < WARPS_PER_BLOCK; i++) sum += s_warp[i];
        g_partials[blockIdx.x] = sum;
        // Release-ordered ticket (no gpu-scope MEMBAR -> no L1D flush).
        unsigned int old;
        asm volatile("atom.acq_rel.gpu.global.add.u32 %0, [%1], 1;"
                     : "=r"(old) : "l"(&g_ticket) : "memory");
        s_is_last = (old == (unsigned int)(NBLOCKS - 1));
    }
    __syncthreads();
    if (!s_is_last) return;

    // ---- last block: reduce 1024 partials (L2-resident), fixed order ----
    __shared__ float s_red[THREADS];
    float sum = 0.f;
    #pragma unroll
    for (int k = 0; k < NBLOCKS / THREADS; k++)
        sum += __ldcg(&g_partials[threadIdx.x + k * THREADS]);
    s_red[threadIdx.x] = sum;
    __syncthreads();
    #pragma unroll
    for (int off = THREADS / 2; off; off >>= 1) {
        if (threadIdx.x < off) s_red[threadIdx.x] += s_red[threadIdx.x + off];
        __syncthreads();
    }
    if (threadIdx.x == 0) {
        int cnt = 0;
        #pragma unroll
        for (int i = 0; i < B; i++) cnt += __ldg(&lengths[i]);
        out[0] = s_red[0] / (float)cnt;
        g_ticket = 0;   // reset for next graph replay
    }
}

extern "C" void kernel_launch(void* const* d_in, const int* in_sizes, int n_in,
                              void* d_out, int out_size) {
    const float* preds   = (const float*)d_in[0];
    const float* targets = (const float*)d_in[1];
    const int*   lengths = (const int*)d_in[2];
    float* out = (float*)d_out;

    triplet_floor_kernel<<<NBLOCKS, THREADS>>>(preds, targets, lengths, out);
}